// round 9
// baseline (speedup 1.0000x reference)
#include <cuda_runtime.h>
#include <math.h>
#include <stdint.h>

#define DK 256
#define DEMB 768
#define CH 32
#define TMAX 1000
#define PMAX 200
#define NCHS_MAX 32
#define NCHP_MAX 7

#define S_DECAY 0.95f
#define P_DECAY 0.99f
#define ALPHA   0.1f
#define BETA    1.0f
#define EPSN    1e-12f
#define NANBITS 0x7fc00000u

// ---------------- device scratch ----------------
__device__ float g_K [TMAX*DK];   // raw K
__device__ float g_Kn[TMAX*DK];   // normalized K
__device__ float g_PK[PMAX*DK];   // normalized PK
__device__ float g_PV[PMAX*DK];   // paragraph V (para_emb @ Wv + bv)
__device__ float g_W[(NCHS_MAX + 2*NCHP_MAX)*CH*DK];
__device__ float g_c[NCHP_MAX*CH];
__device__ float g_res[4*DK];
__device__ float g_wvm[DEMB];              // column-mean of Wv
__device__ float g_u1p[NCHS_MAX*DEMB];     // per-chunk partials of u1 = sum c1_t emb_t
__device__ float g_y[3*DK];                // GEMV thirds of u1 @ Wv
__device__ unsigned g_c1b[TMAX];           // sentence V-coefficients (bits; NaN = not ready)
__device__ int g_bar1 = 0, g_bar2 = 0, g_done = 0, g_u1cnt = 0;

// ---------------- helpers ----------------
__device__ __forceinline__ unsigned long long pack2(float lo, float hi) {
    unsigned long long r;
    asm("mov.b64 %0, {%1, %2};" : "=l"(r) : "f"(lo), "f"(hi));
    return r;
}
__device__ __forceinline__ unsigned long long fma2(unsigned long long a,
                                                   unsigned long long b,
                                                   unsigned long long c) {
    unsigned long long d;
    asm("fma.rn.f32x2 %0, %1, %2, %3;" : "=l"(d) : "l"(a), "l"(b), "l"(c));
    return d;
}
__device__ __forceinline__ void unpack2(unsigned long long v, float& lo, float& hi) {
    asm("mov.b64 {%0, %1}, %2;" : "=f"(lo), "=f"(hi) : "l"(v));
}
__device__ __forceinline__ uint32_t smem_u32(const void* p) {
    uint32_t a;
    asm("{ .reg .u64 t; cvta.to.shared.u64 t, %1; cvt.u32.u64 %0, t; }" : "=r"(a) : "l"(p));
    return a;
}
__device__ __forceinline__ void mbar_init(uint32_t a, uint32_t n) {
    asm volatile("mbarrier.init.shared.b64 [%0], %1;" :: "r"(a), "r"(n) : "memory");
}
__device__ __forceinline__ void mbar_inval(uint32_t a) {
    asm volatile("mbarrier.inval.shared.b64 [%0];" :: "r"(a) : "memory");
}
__device__ __forceinline__ void mbar_expect(uint32_t a, uint32_t bytes) {
    asm volatile("mbarrier.arrive.expect_tx.shared.b64 _, [%0], %1;" :: "r"(a), "r"(bytes) : "memory");
}
__device__ __forceinline__ void bulk_g2s(uint32_t dst, const void* src, uint32_t bytes, uint32_t mbar) {
    asm volatile("cp.async.bulk.shared::cluster.global.mbarrier::complete_tx::bytes [%0], [%1], %2, [%3];"
                 :: "r"(dst), "l"(src), "r"(bytes), "r"(mbar) : "memory");
}
__device__ __forceinline__ void mbar_wait(uint32_t a, uint32_t parity) {
    asm volatile(
        "{\n\t.reg .pred P;\n"
        "W_%=:\n\t"
        "mbarrier.try_wait.parity.acquire.cta.shared::cta.b64 P, [%0], %1, 0x989680;\n\t"
        "@P bra.uni D_%=;\n\t"
        "bra.uni W_%=;\n"
        "D_%=:\n\t}"
        :: "r"(a), "r"(parity) : "memory");
}

// ---------------- dyn smem layout ----------------
#define ETILE 32
#define NSTAGE (DEMB / ETILE)     // 24
#define NBUF 3
#define WBUF_FLOATS (ETILE*DK)    // 8192 floats = 32KB (one matrix per stage now)
#define EST_OFF (NBUF*WBUF_FLOATS)        // 24576
#define DYN_FLOATS (EST_OFF + DEMB*8)     // 30720
#define DYN_BYTES (DYN_FLOATS*4)          // 122880

// ---------------- phase 1: K projection + wvm ----------------
__device__ __forceinline__ void kv_phase(float* dyn, unsigned long long* mb,
                     const float* __restrict__ emb,
                     const float* __restrict__ Wk, const float* __restrict__ bk,
                     const float* __restrict__ Wv, int T)
{
    float* wbuf = dyn;
    float* est  = dyn + EST_OFF;

    const int tid = threadIdx.x, wid = tid >> 5, lane = tid & 31;
    const int r0  = blockIdx.x * 8;
    const int rows = min(8, T - r0);
    const uint32_t wbufb = smem_u32(wbuf);
    const int s0 = blockIdx.x % NSTAGE;

    // distributed wvm: warp w<7 handles Wv row 7*bid + w
    if (wid < 7) {
        int row = blockIdx.x * 7 + wid;
        if (row < DEMB) {
            float s = 0.f;
            #pragma unroll
            for (int k = 0; k < 8; k++) s += Wv[row*DK + lane + 32*k];
            #pragma unroll
            for (int o = 16; o; o >>= 1) s += __shfl_xor_sync(0xffffffffu, s, o);
            if (lane == 0) g_wvm[row] = s * (1.f/256.f);
        }
    }

    for (int idx = tid; idx < 8*DEMB; idx += 256) {
        int e = idx >> 3, r = idx & 7;
        est[e*8 + r] = (r < rows) ? emb[(r0 + r)*DEMB + e] : 0.f;
    }
    if (tid == 0) {
        #pragma unroll
        for (int i = 0; i < NBUF; i++) mbar_init(smem_u32(&mb[i]), 1);
    }
    __syncthreads();

    auto issue = [&](int i) {
        int s = s0 + i; if (s >= NSTAGE) s -= NSTAGE;
        int buf = i % NBUF;
        uint32_t mba = smem_u32(&mb[buf]);
        uint32_t dst = wbufb + (uint32_t)buf * (WBUF_FLOATS*4u);
        mbar_expect(mba, WBUF_FLOATS*4u);
        bulk_g2s(dst, Wk + s*ETILE*DK, WBUF_FLOATS*4u, mba);
    };
    if (tid == 0) { issue(0); issue(1); issue(2); }

    unsigned long long aK[4];
    #pragma unroll
    for (int p = 0; p < 4; p++) aK[p] = pack2(0.f, 0.f);

    for (int i = 0; i < NSTAGE; i++) {
        int s = s0 + i; if (s >= NSTAGE) s -= NSTAGE;
        mbar_wait(smem_u32(&mb[i % NBUF]), (i / NBUF) & 1);
        const float* Wks = wbuf + (i % NBUF) * WBUF_FLOATS;
        const int e0 = s * ETILE;

        #pragma unroll 16
        for (int ee = 0; ee < ETILE; ee++) {
            float wk = Wks[ee*DK + tid];
            unsigned long long wk2 = pack2(wk, wk);
            const float* ep = &est[(e0 + ee)*8];
            ulonglong2 p01 = *(const ulonglong2*)ep;
            ulonglong2 p23 = *(const ulonglong2*)(ep + 4);
            aK[0] = fma2(p01.x, wk2, aK[0]);
            aK[1] = fma2(p01.y, wk2, aK[1]);
            aK[2] = fma2(p23.x, wk2, aK[2]);
            aK[3] = fma2(p23.y, wk2, aK[3]);
        }
        __syncthreads();
        if (tid == 0 && i + NBUF < NSTAGE) issue(i + NBUF);
    }

    float bkv = bk[tid];
    #pragma unroll
    for (int p = 0; p < 4; p++) {
        float k0, k1;
        unpack2(aK[p], k0, k1);
        int r = 2*p;
        if (r < rows)     g_K[(r0+r  )*DK + tid] = k0 + bkv;
        if (r + 1 < rows) g_K[(r0+r+1)*DK + tid] = k1 + bkv;
    }
}

// ---------------- phase 2a: prep (Pm via wvm; no V) ----------------
__device__ __forceinline__ void prep_phase(float* dyn, int cid,
                                           const float* __restrict__ emb,
                                           const float* __restrict__ bv,
                                           int T, int P, int nchS, int nchP)
{
    float* ks  = dyn;             // 32*260
    float* Gs  = dyn + 8320;      // 32*33
    float* Ts  = dyn + 9376;      // 32*36
    float* Pm  = dyn + 10560;     // 32 (pad to 16B boundary below)
    float* fs  = dyn + 10592;
    float* lfs = dyn + 10624;

    const int tid = threadIdx.x;
    const int wid = tid >> 5, lane = tid & 31;

    int type, chunk, steps;
    if (cid < nchS)              { type = 0; chunk = cid;               steps = T; }
    else if (cid < nchS + nchP)  { type = 1; chunk = cid - nchS;        steps = P; }
    else                         { type = 2; chunk = cid - nchS - nchP; steps = P; }
    const int lo  = chunk * CH;
    const int len = min(CH, steps - lo);
    const bool bwd = (type <= 1);
    const bool isPara = (type >= 1);

    if (!isPara) {
        #pragma unroll
        for (int u = 0; u < 8; u++) {
            int id = tid + 256*u;
            int a = id >> 6, c4 = (id & 63) * 4;
            float4 v = make_float4(0.f, 0.f, 0.f, 0.f);
            if (a < len) v = *(const float4*)&g_K[(lo + a)*DK + c4];
            *(float4*)&ks[a*260 + c4] = v;
        }
    } else {
        // PK = 5-group means of raw K
        #pragma unroll
        for (int g = 0; g < 8; g++) {
            int r  = (tid >> 6) + 4*g;
            int c4 = (tid & 63) * 4;
            float4 ak = make_float4(0.f,0.f,0.f,0.f);
            if (r < len) {
                #pragma unroll
                for (int i = 0; i < 5; i++) {
                    float4 kk = *(const float4*)&g_K[((lo + r)*5 + i)*DK + c4];
                    ak.x += kk.x; ak.y += kk.y; ak.z += kk.z; ak.w += kk.w;
                }
                ak.x *= 0.2f; ak.y *= 0.2f; ak.z *= 0.2f; ak.w *= 0.2f;
            }
            *(float4*)&ks[r*260 + c4] = ak;
        }
    }

    // type 2: Pm[r] = 0.2 * sum_{i<5} emb[5(lo+r)+i] . wvm + bvm
    if (type == 2) {
        float bvm;
        {
            float s = 0.f;
            #pragma unroll
            for (int k = 0; k < 8; k++) s += bv[lane + 32*k];
            #pragma unroll
            for (int o = 16; o; o >>= 1) s += __shfl_xor_sync(0xffffffffu, s, o);
            bvm = s * (1.f/256.f);
        }
        #pragma unroll
        for (int rr = 0; rr < 4; rr++) {
            int r = wid + 8*rr;
            float acc = 0.f;
            if (r < len) {
                int para = lo + r;
                for (int i = 0; i < 5; i++) {
                    const float* er = emb + (size_t)(para*5 + i)*DEMB;
                    #pragma unroll
                    for (int k = 0; k < 24; k++) {
                        int e = lane + 32*k;
                        acc += er[e] * g_wvm[e];
                    }
                }
            }
            #pragma unroll
            for (int o = 16; o; o >>= 1) acc += __shfl_xor_sync(0xffffffffu, acc, o);
            if (lane == 0) Pm[r] = 0.2f*acc + bvm;
        }
    }
    __syncthreads();

    // normalize rows; write g_Kn (sentence) / g_PK (para-bwd)
    {
        float* gout = isPara ? g_PK : g_Kn;
        const bool wr = (type != 2);
        #pragma unroll
        for (int rr = 0; rr < 4; rr++) {
            int r = wid*4 + rr;
            float v[8]; float s = 0.f;
            #pragma unroll
            for (int m = 0; m < 8; m++) { v[m] = ks[r*260 + lane + 32*m]; s += v[m]*v[m]; }
            #pragma unroll
            for (int o = 16; o; o >>= 1) s += __shfl_xor_sync(0xffffffffu, s, o);
            float rinv = 1.f / fmaxf(sqrtf(s), EPSN);
            #pragma unroll
            for (int m = 0; m < 8; m++) {
                float nv = v[m] * rinv;
                ks[r*260 + lane + 32*m] = nv;
                if (wr && r < len) gout[(lo + r)*DK + lane + 32*m] = nv;
            }
        }
    }
    __syncthreads();

    // Gram
    {
        float acc[4] = {0.f, 0.f, 0.f, 0.f};
        #pragma unroll 8
        for (int i4 = 0; i4 < 64; i4++) {
            float4 own = *(const float4*)&ks[lane*260 + i4*4];
            #pragma unroll
            for (int s = 0; s < 4; s++) {
                float4 b = *(const float4*)&ks[(wid + 8*s)*260 + i4*4];
                acc[s] += own.x*b.x + own.y*b.y + own.z*b.z + own.w*b.w;
            }
        }
        #pragma unroll
        for (int s = 0; s < 4; s++) Gs[(wid + 8*s)*33 + lane] = acc[s];
    }
    __syncthreads();

    // triangular inverse of (I + alpha*L), scan order
    #pragma unroll
    for (int cc = 0; cc < 4; cc++) {
        int k = wid*4 + cc;
        float v = (lane == k) ? 1.f : 0.f;
        for (int i = 0; i < len; i++) {
            float vi = __shfl_sync(0xffffffffu, v, i);
            if (lane > i && lane < len) {
                float g = bwd ? Gs[(len-1-lane)*33 + (len-1-i)]
                              : Gs[lane*33 + i];
                v -= ALPHA * g * vi;
            }
        }
        Ts[lane*36 + k] = v;
    }
    __syncthreads();

    if (type == 2 && wid == 0) {
        float f = 0.f;
        if (lane < len) {
            float dp = 1.f;
            for (int i = 0; i <= lane; i++) dp *= (1.f / P_DECAY);
            f = BETA * dp * Pm[lane];
        }
        fs[lane] = f;
        __syncwarp();
        float lf = 0.f;
        if (lane < len)
            for (int i = 0; i < lane; i++) lf += Gs[lane*33 + i] * fs[i];
        lfs[lane] = lf;
        __syncwarp();
        float e = 0.f;
        #pragma unroll 8
        for (int k2 = 0; k2 < CH; k2++) e += Ts[lane*36 + k2] * lfs[k2];
        g_c[chunk*CH + lane] = -ALPHA * e + f;
    }

    // W = T * K-chunk (scan order)
    float ksv[CH];
    #pragma unroll
    for (int m = 0; m < CH; m++) {
        int rl = bwd ? (len - 1 - m) : m;
        ksv[m] = (m < len) ? ks[rl*260 + tid] : 0.f;
    }
    float* Wout = g_W + (size_t)cid * CH * DK;
    #pragma unroll
    for (int j = 0; j < CH; j++) {
        float acc2 = 0.f;
        #pragma unroll
        for (int m4 = 0; m4 < 8; m4++) {
            float4 t = *(const float4*)&Ts[j*36 + m4*4];
            acc2 += t.x*ksv[m4*4] + t.y*ksv[m4*4+1] + t.z*ksv[m4*4+2] + t.w*ksv[m4*4+3];
        }
        Wout[j*DK + tid] = acc2;
    }
}

// ---------------- phase 2b: PV = para_emb @ Wv + bv (4 paras per block) ----------------
__device__ __forceinline__ void pv_phase(float* dyn, unsigned long long* mb, int pb,
                     const float* __restrict__ emb,
                     const float* __restrict__ Wv, const float* __restrict__ bv,
                     int T, int P)
{
    float* wbuf = dyn;
    float* pest = dyn + EST_OFF;     // pest[e*8 + r], r<4
    const int tid = threadIdx.x;
    const uint32_t wbufb = smem_u32(wbuf);
    const int p0 = pb * 4;

    // pb==0 re-arms the c1 NaN sentinels for this replay
    if (pb == 0) {
        for (int i = tid; i < T; i += 256) g_c1b[i] = NANBITS;
    }

    #pragma unroll
    for (int r = 0; r < 4; r++) {
        int para = p0 + r;
        #pragma unroll
        for (int k = 0; k < 3; k++) {
            float s = 0.f;
            if (para < P) {
                #pragma unroll
                for (int i = 0; i < 5; i++)
                    s += emb[(size_t)(para*5 + i)*DEMB + tid + 256*k];
            }
            pest[(tid + 256*k)*8 + r] = 0.2f * s;
        }
    }
    if (tid == 0) {
        #pragma unroll
        for (int i = 0; i < NBUF; i++) {
            mbar_inval(smem_u32(&mb[i]));
            mbar_init(smem_u32(&mb[i]), 1);
        }
    }
    __syncthreads();

    auto issue = [&](int s) {
        int buf = s % NBUF;
        uint32_t mba = smem_u32(&mb[buf]);
        uint32_t dst = wbufb + (uint32_t)buf * (WBUF_FLOATS*4u);
        mbar_expect(mba, WBUF_FLOATS*4u);
        bulk_g2s(dst, Wv + s*ETILE*DK, WBUF_FLOATS*4u, mba);
    };
    if (tid == 0) { issue(0); issue(1); issue(2); }

    unsigned long long acc[2] = { pack2(0.f,0.f), pack2(0.f,0.f) };

    for (int s = 0; s < NSTAGE; s++) {
        mbar_wait(smem_u32(&mb[s % NBUF]), (s / NBUF) & 1);
        const float* Wvs = wbuf + (s % NBUF) * WBUF_FLOATS;
        const int e0 = s * ETILE;
        #pragma unroll 16
        for (int ee = 0; ee < ETILE; ee++) {
            float wv = Wvs[ee*DK + tid];
            unsigned long long wv2 = pack2(wv, wv);
            ulonglong2 pr = *(const ulonglong2*)&pest[(e0 + ee)*8];
            acc[0] = fma2(pr.x, wv2, acc[0]);
            acc[1] = fma2(pr.y, wv2, acc[1]);
        }
        __syncthreads();
        if (tid == 0 && s + NBUF < NSTAGE) issue(s + NBUF);
    }

    float bb = bv[tid];
    #pragma unroll
    for (int p = 0; p < 2; p++) {
        float v0, v1;
        unpack2(acc[p], v0, v1);
        int para = p0 + 2*p;
        if (para < P)     g_PV[(size_t)para*DK + tid]     = v0 + bb;
        if (para + 1 < P) g_PV[(size_t)(para+1)*DK + tid] = v1 + bb;
    }
}

// ---------------- phase 3: scans + c1 publish + helpers + GEMV + final ----------------
__device__ __forceinline__ float bred256(float x, float* red)
{
    const int tid = threadIdx.x;
    #pragma unroll
    for (int o = 16; o; o >>= 1) x += __shfl_xor_sync(0xffffffffu, x, o);
    __syncthreads();
    if ((tid & 31) == 0) red[tid >> 5] = x;
    __syncthreads();
    float s = 0.f;
    #pragma unroll
    for (int w = 0; w < 8; w++) s += red[w];
    return s;
}

__device__ __forceinline__ void helper_phase(float* dyn, int k,
                                             const float* __restrict__ emb, int T, int nchS)
{
    if (k >= nchS) return;
    float* c1s = dyn;
    const int tid = threadIdx.x;
    const int lo = k * CH;
    const int len = min(CH, T - lo);

    if (tid < len) {
        volatile unsigned* p = &g_c1b[lo + tid];
        unsigned v;
        do { v = *p; } while (v == NANBITS);
        c1s[tid] = __uint_as_float(v);
    } else if (tid < CH) c1s[tid] = 0.f;
    __syncthreads();

    float a0 = 0.f, a1 = 0.f, a2 = 0.f;
    for (int j = 0; j < len; j++) {
        const float* er = emb + (size_t)(lo + j)*DEMB;
        float cc = c1s[j];
        a0 += cc * er[tid];
        a1 += cc * er[tid + 256];
        a2 += cc * er[tid + 512];
    }
    g_u1p[(size_t)k*DEMB + tid]       = a0;
    g_u1p[(size_t)k*DEMB + tid + 256] = a1;
    g_u1p[(size_t)k*DEMB + tid + 512] = a2;
    __threadfence();
    __syncthreads();
    if (tid == 0) atomicAdd(&g_u1cnt, 1);
}

__device__ __forceinline__ void scan_phase(float* dyn, int bid,
                                           const float* __restrict__ q,
                                           const float* __restrict__ Wv,
                                           const float* __restrict__ bv,
                                           float* __restrict__ out,
                                           int T, int P, int nchS, int nchP)
{
    float* a_s    = dyn;            // 256 (reused as ue for GEMV)
    float* sigk_s = dyn + 256;
    float* sigv_s = dyn + 288;
    float* dpow   = dyn + 320;      // 33
    float* red    = dyn + 356;      // 8
    float* s_invp = dyn + 364;

    const int tid = threadIdx.x;
    const int wid = tid >> 5, lane = tid & 31;
    const bool fwd  = (bid == 3);
    const bool sent = (bid == 0);
    const bool hasV = (bid == 1 || bid == 2);
    const float decay = sent ? S_DECAY : P_DECAY;
    const int nch   = sent ? nchS : nchP;
    const int steps = sent ? T : P;
    const float* Kd = sent ? g_Kn : g_PK;
    const int slot0 = sent ? 0 : (fwd ? (nchS + nchP) : nchS);

    if (tid == 0) {
        dpow[0] = 1.f;
        for (int i = 0; i < CH; i++) dpow[i+1] = dpow[i] * decay;
    }
    __syncthreads();

    float qv = q[tid];
    {
        float x = qv * qv;
        #pragma unroll
        for (int o = 16; o; o >>= 1) x += __shfl_xor_sync(0xffffffffu, x, o);
        if (lane == 0) red[wid] = x;
        __syncthreads();
        if (tid == 0) {
            float s = 0.f;
            #pragma unroll
            for (int w = 0; w < 8; w++) s += red[w];
            *s_invp = 1.f / fmaxf(sqrtf(s), EPSN);
        }
        __syncthreads();
    }
    float s_inv = *s_invp;
    float a;
    if (bid <= 1)      a = qv * s_inv;
    else if (bid == 2) a = 1.f/256.f;
    else               a = 0.f;
    a_s[tid] = a;

    const int j0 = wid * 4;
    float wreg[4][8];
    float creg[4] = {0.f, 0.f, 0.f, 0.f};
    float csum_loc = 0.f;   // lane0-only: sum of c1 (sentence)

    {
        int chunk = fwd ? 0 : (nch - 1);
        const float* Wp = g_W + (size_t)(slot0 + chunk) * CH * DK;
        #pragma unroll
        for (int r = 0; r < 4; r++)
            #pragma unroll
            for (int m = 0; m < 8; m++)
                wreg[r][m] = Wp[(j0 + r)*DK + lane + 32*m];
        if (fwd) {
            #pragma unroll
            for (int r = 0; r < 4; r++) creg[r] = g_c[chunk*CH + j0 + r];
        }
    }

    float outreg = 0.f;

    for (int c = 0; c < nch; c++) {
        const int chunk = fwd ? c : (nch - 1 - c);
        const int lo  = chunk * CH;
        const int len = min(CH, steps - lo);
        const int hi  = lo + len - 1;
        __syncthreads();

        float kreg[CH], vreg[CH];
        #pragma unroll
        for (int j = 0; j < CH; j++) {
            int row = fwd ? (lo + j) : (hi - j);
            row = max(0, min(row, steps - 1));
            kreg[j] = Kd[row*DK + tid];
            vreg[j] = hasV ? g_PV[row*DK + tid] : 0.f;
        }

        float av[8];
        #pragma unroll
        for (int m = 0; m < 8; m++) av[m] = a_s[lane + 32*m];
        float s[4];
        #pragma unroll
        for (int r = 0; r < 4; r++) {
            float t = 0.f;
            #pragma unroll
            for (int m = 0; m < 8; m++) t += wreg[r][m] * av[m];
            s[r] = t;
        }
        #pragma unroll
        for (int o = 16; o; o >>= 1)
            #pragma unroll
            for (int r = 0; r < 4; r++)
                s[r] += __shfl_xor_sync(0xffffffffu, s[r], o);
        if (lane == 0) {
            #pragma unroll
            for (int r = 0; r < 4; r++) {
                int j = j0 + r;
                float sk = 0.f, sv = 0.f;
                if (j < len) {
                    if (fwd) { sk = -ALPHA * s[r] + creg[r]; }
                    else     { sk = -ALPHA * s[r]; sv = BETA * dpow[j] * s[r]; }
                }
                sigk_s[j] = sk;
                if (sent) {
                    if (j < len) {
                        g_c1b[hi - j] = __float_as_uint(sv);   // publish coefficient
                        csum_loc += sv;
                    }
                } else {
                    sigv_s[j] = sv;
                }
            }
        }

        if (c + 1 < nch) {
            int nchunk = fwd ? (c + 1) : (nch - 2 - c);
            const float* Wp = g_W + (size_t)(slot0 + nchunk) * CH * DK;
            #pragma unroll
            for (int r = 0; r < 4; r++)
                #pragma unroll
                for (int m = 0; m < 8; m++)
                    wreg[r][m] = Wp[(j0 + r)*DK + lane + 32*m];
            if (fwd) {
                #pragma unroll
                for (int r = 0; r < 4; r++) creg[r] = g_c[nchunk*CH + j0 + r];
            }
        }
        __syncthreads();

        float wsum = 0.f, osum = 0.f;
        #pragma unroll
        for (int j = 0; j < CH; j++) {
            wsum += sigk_s[j] * kreg[j];
            if (hasV) osum += sigv_s[j] * vreg[j];
        }
        outreg += osum;
        a = dpow[len] * (a + wsum);
        a_s[tid] = a;
    }

    if (bid != 0) {
        // publish scan result
        if (bid < 3) g_res[bid*DK + tid] = outreg;
        else         g_res[3*DK + tid]   = a;
        __threadfence();
        __syncthreads();

        // wait for all u1 partials, then do our third of u1 @ Wv
        if (tid == 0) { while (*(volatile int*)&g_u1cnt < nchS) { } }
        __syncthreads();
        __threadfence();

        const int e0 = (bid - 1) * 256;
        float ue = 0.f;
        for (int k = 0; k < nchS; k++) ue += g_u1p[(size_t)k*DEMB + e0 + tid];
        __syncthreads();          // a_s free (scan done)
        a_s[tid] = ue;
        __syncthreads();
        float y = 0.f;
        #pragma unroll 8
        for (int e = 0; e < 256; e++)
            y += a_s[e] * Wv[(size_t)(e0 + e)*DK + tid];
        g_y[(bid-1)*DK + tid] = y;
        __threadfence();
        __syncthreads();
        if (tid == 0) atomicAdd(&g_done, 1);
        return;
    }

    // ---- block 0: combine ----
    if (lane == 0) red[wid] = csum_loc;
    __syncthreads();
    float csum = 0.f;
    #pragma unroll
    for (int w = 0; w < 8; w++) csum += red[w];
    __syncthreads();

    if (tid == 0) { while (*(volatile int*)&g_done < 3) { } }
    __syncthreads();
    __threadfence();

    float yv  = g_y[tid] + g_y[DK + tid] + g_y[2*DK + tid];
    float r1  = g_res[1*DK + tid];
    float r2  = g_res[2*DK + tid];
    float dkv = g_res[3*DK + tid];
    float ssd = bred256(dkv*dkv, red);
    float dot = bred256(qv*dkv, red);
    float coef = dot * s_inv / fmaxf(sqrtf(ssd), EPSN);
    out[tid] = 0.2f*(yv + csum*bv[tid]) + 0.3f*r1 + 0.5f*(BETA*coef)*r2;

    __syncthreads();
    if (tid == 0) { g_bar1 = 0; g_bar2 = 0; g_done = 0; g_u1cnt = 0; }
}

// ---------------- the single fused kernel ----------------
__global__ void __launch_bounds__(256, 1) k_mega(
                     const float* __restrict__ emb, const float* __restrict__ q,
                     const float* __restrict__ Wk, const float* __restrict__ bk,
                     const float* __restrict__ Wv, const float* __restrict__ bv,
                     float* __restrict__ out,
                     int T, int P, int nchS, int nchP, int nKV, int nPrep, int nP2)
{
    extern __shared__ __align__(16) float dyn[];
    __shared__ __align__(8) unsigned long long mb[NBUF];

    const int bid = blockIdx.x, tid = threadIdx.x;

    // ---- phase 1 ----
    kv_phase(dyn, mb, emb, Wk, bk, Wv, T);

    __threadfence();
    __syncthreads();
    if (tid == 0) atomicAdd(&g_bar1, 1);
    if (bid >= nP2) return;
    if (tid == 0) { while (*(volatile int*)&g_bar1 < nKV) { } }
    __threadfence();
    __syncthreads();

    // ---- phase 2 ----
    if (bid < nPrep) prep_phase(dyn, bid, emb, bv, T, P, nchS, nchP);
    else             pv_phase(dyn, mb, bid - nPrep, emb, Wv, bv, T, P);

    __threadfence();
    __syncthreads();
    if (tid == 0) atomicAdd(&g_bar2, 1);
    if (bid >= 4 + nchS) return;
    if (tid == 0) { while (*(volatile int*)&g_bar2 < nP2) { } }
    __threadfence();
    __syncthreads();

    // ---- phase 3 ----
    if (bid < 4) scan_phase(dyn, bid, q, Wv, bv, out, T, P, nchS, nchP);
    else         helper_phase(dyn, bid - 4, emb, T, nchS);
}

// ---------------- launcher ----------------
extern "C" void kernel_launch(void* const* d_in, const int* in_sizes, int n_in,
                              void* d_out, int out_size)
{
    const float* emb = (const float*)d_in[0];
    const float* q   = (const float*)d_in[1];
    const float* Wk  = (const float*)d_in[2];
    const float* bk  = (const float*)d_in[3];
    const float* Wv  = (const float*)d_in[4];
    const float* bv  = (const float*)d_in[5];
    // d_in[6..8] = zero initial memories (collapsed analytically)

    int T = in_sizes[0] / DEMB;     // 1000
    int P = T / 5;                  // 200
    int nchS = (T + CH - 1) / CH;   // 32
    int nchP = (P + CH - 1) / CH;   // 7
    int nKV  = (T + 7) / 8;         // 125 (single wave, all co-resident)
    int nPrep = nchS + 2*nchP;      // 46
    int nPV  = (P + 3) / 4;         // 50
    int nP2  = nPrep + nPV;         // 96

    cudaFuncSetAttribute(k_mega, cudaFuncAttributeMaxDynamicSharedMemorySize, DYN_BYTES);

    k_mega<<<nKV, 256, DYN_BYTES>>>(emb, q, Wk, bk, Wv, bv, (float*)d_out,
                                    T, P, nchS, nchP, nKV, nPrep, nP2);
}